// round 9
// baseline (speedup 1.0000x reference)
#include <cuda_runtime.h>

// InvDiff: x[64, 4096, 256] fp32
//   d[b,l,f] = x[b,l+1,f] - x[b,l,f]                 (l in [0,4095))
//   y[b,l,f] = x[b,l+1,f] - x[b,0,f]  (l<4094), 0    (l==4094)
// Output = [d flat | y flat]. HBM-ceiling-bound (~6.5 TB/s, traffic at floor).
// This round: 256-bit vector memory ops (sm_100+ v8.f32). One warp = one 1KB
// row; each lane moves 32B per instruction. Warp handles an l-pair:
// 3 row-loads -> 2 d-rows + 2 y-rows, maximally contiguous per instruction.

static constexpr int B  = 64;
static constexpr int L  = 4096;
static constexpr int F  = 256;
static constexpr int LD = L - 1;          // 4095 output rows

__device__ __forceinline__ void ldg8(const float* p, float* v) {
    asm volatile("ld.global.nc.v8.f32 {%0,%1,%2,%3,%4,%5,%6,%7}, [%8];"
                 : "=f"(v[0]), "=f"(v[1]), "=f"(v[2]), "=f"(v[3]),
                   "=f"(v[4]), "=f"(v[5]), "=f"(v[6]), "=f"(v[7])
                 : "l"(p));
}

__device__ __forceinline__ void stg8(float* p, const float* v) {
    asm volatile("st.global.v8.f32 [%0], {%1,%2,%3,%4,%5,%6,%7,%8};"
                 :: "l"(p),
                    "f"(v[0]), "f"(v[1]), "f"(v[2]), "f"(v[3]),
                    "f"(v[4]), "f"(v[5]), "f"(v[6]), "f"(v[7])
                 : "memory");
}

__global__ __launch_bounds__(256)
void invdiff_kernel(const float* __restrict__ x, float* __restrict__ out) {
    const int lane = threadIdx.x;                    // 0..31
    const int w    = blockIdx.y * blockDim.y + threadIdx.y;   // warp index
    const int l0   = w * 2;                          // even row
    const int b    = blockIdx.z;
    if (l0 >= LD) return;

    const int fo     = lane * 8;                     // float offset in row
    const int baseIn = b * (L * F);
    const bool has2  = (l0 + 1) < LD;

    float x0[8], xa[8], xb[8], xc[8];
    // Front-batched loads. x0 (row 0) is a 1KB/batch L2-hot broadcast.
    ldg8(x + baseIn + fo, x0);
    ldg8(x + baseIn +  l0      * F + fo, xa);
    ldg8(x + baseIn + (l0 + 1) * F + fo, xb);
    if (has2) ldg8(x + baseIn + (l0 + 2) * F + fo, xc);

    const long outIdx = (long)b * (LD * F) + (long)l0 * F + fo;
    const long D      = (long)B * LD * F;            // float count of d block

    float t[8];

    // d row l0
#pragma unroll
    for (int i = 0; i < 8; i++) t[i] = xb[i] - xa[i];
    stg8(out + outIdx, t);

    // d row l0+1
    if (has2) {
#pragma unroll
        for (int i = 0; i < 8; i++) t[i] = xc[i] - xb[i];
        stg8(out + outIdx + F, t);
    }

    // y row l0
    if (l0 < LD - 1) {
#pragma unroll
        for (int i = 0; i < 8; i++) t[i] = xb[i] - x0[i];
    } else {
#pragma unroll
        for (int i = 0; i < 8; i++) t[i] = 0.f;
    }
    stg8(out + D + outIdx, t);

    // y row l0+1
    if (has2) {
        if (l0 + 1 < LD - 1) {
#pragma unroll
            for (int i = 0; i < 8; i++) t[i] = xc[i] - x0[i];
        } else {
#pragma unroll
            for (int i = 0; i < 8; i++) t[i] = 0.f;
        }
        stg8(out + D + outIdx + F, t);
    }
}

extern "C" void kernel_launch(void* const* d_in, const int* in_sizes, int n_in,
                              void* d_out, int out_size) {
    const float* x = (const float*)d_in[0];
    float* out = (float*)d_out;

    // 2048 l-pairs; 8 warps (pairs) per block
    dim3 block(32, 8, 1);                            // 256 threads
    dim3 grid(1, (2048 + 7) / 8, B);                 // 256 x 64 blocks
    invdiff_kernel<<<grid, block>>>(x, out);
}

// round 10
// speedup vs baseline: 1.0077x; 1.0077x over previous
#include <cuda_runtime.h>

// InvDiff: x[64, 4096, 256] fp32
//   d[b,l,f] = x[b,l+1,f] - x[b,l,f]                 (l in [0,4095))
//   y[b,l,f] = x[b,l+1,f] - x[b,0,f]  (l<4094), 0    (l==4094)
// Output = [d flat | y flat].
//
// FINAL (freeze): HBM-ceiling-bound. Traffic is at the analytic floor
// (268MB R + 536MB W; ~747MB measured after L2 carry-over) and six
// structurally distinct variants (store policies, vector widths, stream
// splitting, RPT 1..4, occupancy 59-82%) all measure 6.37-6.51 TB/s.
// This is the best-measured variant: RPT=2, L2::256B read promotion,
// 512-thread blocks, predication-free bulk path. 119.3us / 6510 GB/s.

static constexpr int B   = 64;
static constexpr int L   = 4096;
static constexpr int F   = 256;
static constexpr int F4  = F / 4;         // 64 float4 per row
static constexpr int LD  = L - 1;         // 4095 output rows

__device__ __forceinline__ float4 ldg256(const float4* p) {
    float4 v;
    asm volatile("ld.global.nc.L2::256B.v4.f32 {%0,%1,%2,%3}, [%4];"
                 : "=f"(v.x), "=f"(v.y), "=f"(v.z), "=f"(v.w)
                 : "l"(p));
    return v;
}

__device__ __forceinline__ float4 sub4(float4 a, float4 b) {
    float4 r; r.x = a.x - b.x; r.y = a.y - b.y; r.z = a.z - b.z; r.w = a.w - b.w;
    return r;
}

__global__ __launch_bounds__(512)
void invdiff_kernel(const float4* __restrict__ x, float4* __restrict__ out) {
    const int f  = threadIdx.x;                                   // 0..63
    const int l0 = (blockIdx.y * blockDim.y + threadIdx.y) * 2;   // even row
    const int b  = blockIdx.z;
    if (l0 >= LD) return;

    const int baseIn = b * (L * F4);
    const int outIdx = b * (LD * F4) + l0 * F4 + f;
    const int D      = B * LD * F4;       // float4 count of d block

    const float4 x0 = __ldg(&x[baseIn + f]);   // 1KB/batch broadcast, cache-hot

    if (l0 + 2 < LD) {
        // Bulk path: no predication, 3 front-batched promoted loads.
        const float4 xa = ldg256(&x[baseIn +  l0      * F4 + f]);
        const float4 xb = ldg256(&x[baseIn + (l0 + 1) * F4 + f]);
        const float4 xc = ldg256(&x[baseIn + (l0 + 2) * F4 + f]);

        out[outIdx]          = sub4(xb, xa);
        out[outIdx + F4]     = sub4(xc, xb);
        out[D + outIdx]      = sub4(xb, x0);
        out[D + outIdx + F4] = sub4(xc, x0);
    } else {
        // Tail: rows near l = LD-1 (y's last row is zero; d may lack row 2).
        const float4 xa = __ldg(&x[baseIn + l0 * F4 + f]);
        const float4 xb = __ldg(&x[baseIn + (l0 + 1) * F4 + f]);

        out[outIdx] = sub4(xb, xa);
        float4 y0;
        if (l0 < LD - 1) y0 = sub4(xb, x0);
        else { y0.x = 0.f; y0.y = 0.f; y0.z = 0.f; y0.w = 0.f; }
        out[D + outIdx] = y0;

        if (l0 + 1 < LD) {
            const float4 xc = __ldg(&x[baseIn + (l0 + 2) * F4 + f]);
            out[outIdx + F4] = sub4(xc, xb);
            float4 y1;
            if (l0 + 1 < LD - 1) y1 = sub4(xc, x0);
            else { y1.x = 0.f; y1.y = 0.f; y1.z = 0.f; y1.w = 0.f; }
            out[D + outIdx + F4] = y1;
        }
    }
}

extern "C" void kernel_launch(void* const* d_in, const int* in_sizes, int n_in,
                              void* d_out, int out_size) {
    const float4* x = (const float4*)d_in[0];
    float4* out = (float4*)d_out;

    // 2048 l-pairs, 8 pairs per block in y -> 256 blocks in y
    dim3 block(F4, 8, 1);                            // 512 threads
    dim3 grid(1, (2048 + 7) / 8, B);                 // 256 x 64 blocks
    invdiff_kernel<<<grid, block>>>(x, out);
}

// round 11
// speedup vs baseline: 1.0096x; 1.0019x over previous
#include <cuda_runtime.h>

// InvDiff: x[64, 4096, 256] fp32
//   d[b,l,f] = x[b,l+1,f] - x[b,l,f]                 (l in [0,4095))
//   y[b,l,f] = x[b,l+1,f] - x[b,0,f]  (l<4094), 0    (l==4094)
// Output = [d flat | y flat].
//
// FINAL (converged, confirmed by re-bench): HBM-ceiling-bound.
// Traffic at the analytic floor (536MB mandatory writes + ~211MB deduped
// reads); seven structurally distinct variants (store policies, 128/256-bit
// vectors, stream splitting, RPT 1-4, occupancy 59-82%) all measure
// 6.37-6.51 TB/s -> the LTS/HBM mixed-stream path is the limiter, not SMs.
// Best variant: RPT=2, L2::256B read promotion, 512-thread blocks,
// predication-free bulk path. ncu-stable at 114.8-115.0us / 6507-6510 GB/s.

static constexpr int B   = 64;
static constexpr int L   = 4096;
static constexpr int F   = 256;
static constexpr int F4  = F / 4;         // 64 float4 per row
static constexpr int LD  = L - 1;         // 4095 output rows

__device__ __forceinline__ float4 ldg256(const float4* p) {
    float4 v;
    asm volatile("ld.global.nc.L2::256B.v4.f32 {%0,%1,%2,%3}, [%4];"
                 : "=f"(v.x), "=f"(v.y), "=f"(v.z), "=f"(v.w)
                 : "l"(p));
    return v;
}

__device__ __forceinline__ float4 sub4(float4 a, float4 b) {
    float4 r; r.x = a.x - b.x; r.y = a.y - b.y; r.z = a.z - b.z; r.w = a.w - b.w;
    return r;
}

__global__ __launch_bounds__(512)
void invdiff_kernel(const float4* __restrict__ x, float4* __restrict__ out) {
    const int f  = threadIdx.x;                                   // 0..63
    const int l0 = (blockIdx.y * blockDim.y + threadIdx.y) * 2;   // even row
    const int b  = blockIdx.z;
    if (l0 >= LD) return;

    const int baseIn = b * (L * F4);
    const int outIdx = b * (LD * F4) + l0 * F4 + f;
    const int D      = B * LD * F4;       // float4 count of d block

    const float4 x0 = __ldg(&x[baseIn + f]);   // 1KB/batch broadcast, cache-hot

    if (l0 + 2 < LD) {
        // Bulk path: no predication, 3 front-batched promoted loads.
        const float4 xa = ldg256(&x[baseIn +  l0      * F4 + f]);
        const float4 xb = ldg256(&x[baseIn + (l0 + 1) * F4 + f]);
        const float4 xc = ldg256(&x[baseIn + (l0 + 2) * F4 + f]);

        out[outIdx]          = sub4(xb, xa);
        out[outIdx + F4]     = sub4(xc, xb);
        out[D + outIdx]      = sub4(xb, x0);
        out[D + outIdx + F4] = sub4(xc, x0);
    } else {
        // Tail: rows near l = LD-1 (y's last row is zero; d may lack row 2).
        const float4 xa = __ldg(&x[baseIn + l0 * F4 + f]);
        const float4 xb = __ldg(&x[baseIn + (l0 + 1) * F4 + f]);

        out[outIdx] = sub4(xb, xa);
        float4 y0;
        if (l0 < LD - 1) y0 = sub4(xb, x0);
        else { y0.x = 0.f; y0.y = 0.f; y0.z = 0.f; y0.w = 0.f; }
        out[D + outIdx] = y0;

        if (l0 + 1 < LD) {
            const float4 xc = __ldg(&x[baseIn + (l0 + 2) * F4 + f]);
            out[outIdx + F4] = sub4(xc, xb);
            float4 y1;
            if (l0 + 1 < LD - 1) y1 = sub4(xc, x0);
            else { y1.x = 0.f; y1.y = 0.f; y1.z = 0.f; y1.w = 0.f; }
            out[D + outIdx + F4] = y1;
        }
    }
}

extern "C" void kernel_launch(void* const* d_in, const int* in_sizes, int n_in,
                              void* d_out, int out_size) {
    const float4* x = (const float4*)d_in[0];
    float4* out = (float4*)d_out;

    // 2048 l-pairs, 8 pairs per block in y -> 256 blocks in y
    dim3 block(F4, 8, 1);                            // 512 threads
    dim3 grid(1, (2048 + 7) / 8, B);                 // 256 x 64 blocks
    invdiff_kernel<<<grid, block>>>(x, out);
}